// round 15
// baseline (speedup 1.0000x reference)
#include <cuda_runtime.h>
#include <cuda_fp16.h>
#include <math.h>
#include <stdint.h>

#define MAX_N 100000
#define MAX_E 600000

__device__ float  g_QU  [(size_t)MAX_N * 384];  // q(128)|u0(128)|u1(128) fp32
__device__ float  g_KV  [(size_t)MAX_N * 256];  // k(128)|v(128) fp32
__device__ __half g_xh  [(size_t)MAX_N * 128];  // x in fp16
__device__ __half g_acch[(size_t)MAX_N * 256];  // normalized e-accumulators, fp16
__device__ __half g_BcatTh[768 * 128];          // [n][k] fp16
__device__ float  g_bcat[768];
__device__ __half g_BblkTh[128 * 256];          // [n][k] fp16
__device__ int    g_cnt[MAX_N];
__device__ int    g_off[MAX_N];
__device__ int    g_cur[MAX_N];
__device__ int    g_bsum[256];
__device__ float4 g_epack[MAX_E];               // (src_bits, e_bits, relt, 0) grouped by dst

// ---------------------------------------------------------------------------
// PTX helpers
// ---------------------------------------------------------------------------
__device__ __forceinline__ void cpz(unsigned dst, const void* src, int sz) {
    asm volatile("cp.async.cg.shared.global [%0], [%1], 16, %2;"
                 :: "r"(dst), "l"(src), "r"(sz));
}
__device__ __forceinline__ void mma16h(float* c, const uint32_t* a, const uint32_t* b) {
    asm volatile("mma.sync.aligned.m16n8k16.row.col.f32.f16.f16.f32 "
        "{%0,%1,%2,%3}, {%4,%5,%6,%7}, {%8,%9}, {%0,%1,%2,%3};"
        : "+f"(c[0]), "+f"(c[1]), "+f"(c[2]), "+f"(c[3])
        : "r"(a[0]), "r"(a[1]), "r"(a[2]), "r"(a[3]), "r"(b[0]), "r"(b[1]));
}
__device__ __forceinline__ void ldsm4(uint32_t& r0, uint32_t& r1,
                                      uint32_t& r2, uint32_t& r3, uint32_t addr) {
    asm volatile("ldmatrix.sync.aligned.m8n8.x4.shared.b16 {%0,%1,%2,%3}, [%4];"
        : "=r"(r0), "=r"(r1), "=r"(r2), "=r"(r3) : "r"(addr));
}

// ---------------------------------------------------------------------------
// fp16 GEMM with ldmatrix fragment loads.
// C[M x (128*gridDim.y)] = A[M x K] @ B (+bias)(+=C), fp32 accum.
// BM=128, BN=128, BK=32, 256 thr (8 warps, 4x2), warp tile 64x64, m16n8k16.
// ---------------------------------------------------------------------------
__global__ __launch_bounds__(256) void mma_gemm_h(
    const __half* __restrict__ A, int lda,
    const __half* __restrict__ BT, int ldb,
    float* __restrict__ C,
    int M, int K,
    const float* __restrict__ bias, int accum, int mode)
{
    __shared__ __half As[2][128][40];
    __shared__ __half Bs[2][128][40];
    const int tid = threadIdx.x;
    const int lane = tid & 31;
    const int warp = tid >> 5;
    const int wm = warp & 3, wn = warp >> 2;
    const int grp = lane >> 2, qd = lane & 3;
    const int bm0 = blockIdx.x * 128;
    const int bn0 = blockIdx.y * 128;

    const uint32_t asB = (uint32_t)__cvta_generic_to_shared(&As[0][0][0]);
    const uint32_t bsB = (uint32_t)__cvta_generic_to_shared(&Bs[0][0][0]);
    // ldmatrix lane-address components
    const int a_row = (lane & 7) + ((lane >> 3) & 1) * 8;  // row within 16-row tile
    const int a_koff = (lane >> 4) * 8;                    // 0 or 8 (k halves)
    const int b_row = lane & 7;
    const int b_ntoff = (lane >> 4);                       // 0 or 1 (nt within pair)
    const int b_koff = ((lane >> 3) & 1) * 8;              // 0 or 8

    float c[2][8][4];
#pragma unroll
    for (int i = 0; i < 2; i++)
#pragma unroll
        for (int j = 0; j < 8; j++)
#pragma unroll
            for (int u = 0; u < 4; u++) c[i][j][u] = 0.f;

    const int ntiles = K >> 5;   // BK=32

    auto cpA = [&](int kt, int buf) {
#pragma unroll
        for (int it = 0; it < 2; it++) {
            int idx = tid + 256 * it;
            int row = idx >> 2, ch = (idx & 3) * 8;
            int gr = bm0 + row;
            int grc = gr < M ? gr : (M - 1);
            const __half* src = A + (size_t)grc * lda + kt * 32 + ch;
            unsigned dst = (unsigned)__cvta_generic_to_shared(&As[buf][row][ch]);
            cpz(dst, src, gr < M ? 16 : 0);
        }
    };
    auto cpB = [&](int kt, int buf) {
#pragma unroll
        for (int it = 0; it < 2; it++) {
            int idx = tid + 256 * it;
            int row = idx >> 2, ch = (idx & 3) * 8;
            const __half* src = BT + (size_t)(bn0 + row) * ldb + kt * 32 + ch;
            unsigned dst = (unsigned)__cvta_generic_to_shared(&Bs[buf][row][ch]);
            cpz(dst, src, 16);
        }
    };

    cpA(0, 0); cpB(0, 0);
    asm volatile("cp.async.commit_group;");
    asm volatile("cp.async.wait_group 0;");
    __syncthreads();

    for (int t = 0; t < ntiles; t++) {
        int cur = t & 1, nxt = cur ^ 1;
        bool more = (t + 1 < ntiles);
        if (more) {
            cpA(t + 1, nxt); cpB(t + 1, nxt);
            asm volatile("cp.async.commit_group;");
        }
        uint32_t aOff = asB + cur * 10240;
        uint32_t bOff = bsB + cur * 10240;
#pragma unroll
        for (int kk = 0; kk < 2; kk++) {        // two k16 steps per slab
            int k0 = kk * 16;
            uint32_t af[2][4], bf[8][2];
#pragma unroll
            for (int mt = 0; mt < 2; mt++) {
                uint32_t addr = aOff + (uint32_t)(wm * 32 + mt * 16 + a_row) * 80
                              + (uint32_t)(k0 + a_koff) * 2;
                ldsm4(af[mt][0], af[mt][1], af[mt][2], af[mt][3], addr);
            }
#pragma unroll
            for (int p = 0; p < 4; p++) {       // nt pairs (2p, 2p+1)
                uint32_t addr = bOff + (uint32_t)(wn * 64 + (2 * p + b_ntoff) * 8 + b_row) * 80
                              + (uint32_t)(k0 + b_koff) * 2;
                ldsm4(bf[2 * p][0], bf[2 * p][1], bf[2 * p + 1][0], bf[2 * p + 1][1], addr);
            }
#pragma unroll
            for (int mt = 0; mt < 2; mt++)
#pragma unroll
                for (int nt = 0; nt < 8; nt++)
                    mma16h(c[mt][nt], af[mt], bf[nt]);
        }
        if (more) asm volatile("cp.async.wait_group 0;");
        __syncthreads();
    }

    // Uniform store-target selection (per block)
    float* baseP; int ldo, csub;
    if (mode == 0)      { baseP = C;     ldo = 128; csub = 0;   }
    else if (bn0 < 384) { baseP = g_QU;  ldo = 384; csub = 0;   }
    else if (bn0 < 640) { baseP = g_KV;  ldo = 256; csub = 384; }
    else                { baseP = C;     ldo = 128; csub = 640; }

#pragma unroll
    for (int mt = 0; mt < 2; mt++)
#pragma unroll
        for (int nt = 0; nt < 8; nt++)
#pragma unroll
            for (int hf = 0; hf < 2; hf++) {
                int row = bm0 + wm * 32 + mt * 16 + grp + hf * 8;
                if (row >= M) continue;
                int col = bn0 + wn * 64 + nt * 8 + qd * 2;
                float2 v2;
                v2.x = c[mt][nt][hf * 2 + 0];
                v2.y = c[mt][nt][hf * 2 + 1];
                if (bias) { v2.x += bias[col]; v2.y += bias[col + 1]; }
                float* cp = baseP + (size_t)row * ldo + (col - csub);
                if (accum) { v2.x += cp[0]; v2.y += cp[1]; }
                *(float2*)cp = v2;
            }
}

// ---------------------------------------------------------------------------
// x -> fp16 conversion
// ---------------------------------------------------------------------------
__global__ __launch_bounds__(256) void convx_k(const float* __restrict__ x, int total4)
{
    int i = blockIdx.x * 256 + threadIdx.x;
    if (i >= total4) return;
    float4 v = ((const float4*)x)[i];
    __half2* o = (__half2*)g_xh;
    o[2 * i + 0] = __float22half2_rn(make_float2(v.x, v.y));
    o[2 * i + 1] = __float22half2_rn(make_float2(v.z, v.w));
}

// ---------------------------------------------------------------------------
// Fused prep (fp16 weights). Zeroes g_cnt/g_cur.
// ---------------------------------------------------------------------------
__global__ __launch_bounds__(128) void prep_k(
    const float* __restrict__ Wq, const float* __restrict__ bq,
    const float* __restrict__ Wk, const float* __restrict__ bk,
    const float* __restrict__ Wv, const float* __restrict__ bv,
    const float* __restrict__ Ws, const float* __restrict__ bs,
    const float* __restrict__ We, int N)
{
    int j = blockIdx.x;
    int r = threadIdx.x;

    for (int i = j * 128 + r; i < N; i += 896 * 128) {
        g_cnt[i] = 0;
        g_cur[i] = 0;
    }

    if (j >= 768) {
        int n = j - 768;
#pragma unroll
        for (int kq = 0; kq < 2; kq++) {
            int k = r + kq * 128;
            float v = 0.f;
            if (k < 128) { if (n < 64)  v = We[k * 128 + n]; }
            else         { if (n >= 64) v = We[(k - 128) * 128 + n]; }
            g_BblkTh[n * 256 + k] = __float2half_rn(v);
        }
        return;
    }

    float v;
    if (j < 128) v = Wq[r * 128 + j];
    else if (j < 256) {
        int d = j - 128; const float* w = We + d * 128;
        float s = 0.f;
#pragma unroll
        for (int c = 0; c < 64; c++) s = fmaf(Wq[r * 128 + c], w[c], s);
        v = s;
    } else if (j < 384) {
        int d = j - 256; const float* w = We + d * 128 + 64;
        float s = 0.f;
#pragma unroll
        for (int c = 0; c < 64; c++) s = fmaf(Wq[r * 128 + 64 + c], w[c], s);
        v = s;
    }
    else if (j < 512) v = Wk[r * 128 + (j - 384)];
    else if (j < 640) v = Wv[r * 128 + (j - 512)];
    else              v = Ws[r * 128 + (j - 640)];
    g_BcatTh[j * 128 + r] = __float2half_rn(v);

    if (r == 0) {
        float bv2;
        if (j < 128) bv2 = bq[j];
        else if (j < 256) {
            int d = j - 128; const float* w = We + d * 128;
            float s = 0.f;
            for (int c = 0; c < 64; c++) s = fmaf(bq[c], w[c], s);
            bv2 = s;
        } else if (j < 384) {
            int d = j - 256; const float* w = We + d * 128 + 64;
            float s = 0.f;
            for (int c = 0; c < 64; c++) s = fmaf(bq[64 + c], w[c], s);
            bv2 = s;
        }
        else if (j < 512) bv2 = bk[j - 384];
        else if (j < 640) bv2 = bv[j - 512];
        else              bv2 = bs[j - 640];
        g_bcat[j] = bv2;
    }
}

// ---------------------------------------------------------------------------
// Edge binning (counting sort by dst)
// ---------------------------------------------------------------------------
__global__ __launch_bounds__(256) void hist_k(const int* __restrict__ ei, int E)
{
    int i = blockIdx.x * 256 + threadIdx.x;
    if (i < E) atomicAdd(&g_cnt[ei[E + i]], 1);
}

__global__ __launch_bounds__(512) void scan1_k(int N)
{
    __shared__ int sh[512];
    int tid = threadIdx.x;
    int i = blockIdx.x * 512 + tid;
    int v = (i < N) ? g_cnt[i] : 0;
    sh[tid] = v;
    __syncthreads();
#pragma unroll
    for (int o = 1; o < 512; o <<= 1) {
        int t = (tid >= o) ? sh[tid - o] : 0;
        __syncthreads();
        sh[tid] += t;
        __syncthreads();
    }
    if (i < N) g_off[i] = sh[tid] - v;
    if (tid == 511) g_bsum[blockIdx.x] = sh[511];
}

__global__ __launch_bounds__(256) void scan2_k(int nb)
{
    __shared__ int sh[256];
    int tid = threadIdx.x;
    int v = (tid < nb) ? g_bsum[tid] : 0;
    sh[tid] = v;
    __syncthreads();
#pragma unroll
    for (int o = 1; o < 256; o <<= 1) {
        int t = (tid >= o) ? sh[tid - o] : 0;
        __syncthreads();
        sh[tid] += t;
        __syncthreads();
    }
    if (tid < nb) g_bsum[tid] = sh[tid] - v;
}

__global__ __launch_bounds__(256) void scatter_k(
    const int* __restrict__ ei, const float* __restrict__ lu,
    const float* __restrict__ tt, int E)
{
    int e = blockIdx.x * 256 + threadIdx.x;
    if (e >= E) return;
    int src = ei[e];
    int dst = ei[E + e];
    int base = g_off[dst] + g_bsum[dst >> 9];
    int pos = base + atomicAdd(&g_cur[dst], 1);
    float4 p;
    p.x = __int_as_float(src);
    p.y = __int_as_float(e);
    p.z = lu[src] - tt[e];
    p.w = 0.f;
    g_epack[pos] = p;
}

// ---------------------------------------------------------------------------
// Aggregation: warp per dst node, 2 edges per iteration with joint
// interleaved reductions + pair prefetch.
// ---------------------------------------------------------------------------
__device__ __forceinline__ float coss(float x) {
    float k = rintf(x * 0.15915494309189535f);
    float r = fmaf(k, -6.28125f, x);
    r = fmaf(k, -1.93530717958623e-3f, r);
    return __cosf(r);
}
__device__ __forceinline__ float dot4(float4 a, float4 b) {
    return a.x * b.x + a.y * b.y + a.z * b.z + a.w * b.w;
}
__device__ __forceinline__ float4 fma4(float s, float4 a, float4 acc) {
    acc.x = fmaf(s, a.x, acc.x);
    acc.y = fmaf(s, a.y, acc.y);
    acc.z = fmaf(s, a.z, acc.z);
    acc.w = fmaf(s, a.w, acc.w);
    return acc;
}

__global__ __launch_bounds__(32) void agg_k(
    const float* __restrict__ msg,
    const float* __restrict__ wt, const float* __restrict__ bt,
    float* __restrict__ out, int N)
{
    int n = blockIdx.x;
    int lane = threadIdx.x;
    if (n >= N) return;

    int off = g_off[n] + g_bsum[n >> 9];
    int deg = g_cnt[n];

    const float4* QU4 = (const float4*)(g_QU + (size_t)n * 384);
    float4 q4 = QU4[lane];
    float4 u0 = QU4[32 + lane];
    float4 u1 = QU4[64 + lane];

    float4 w4 = make_float4(0.f, 0.f, 0.f, 0.f), b4 = w4;
    if (lane < 16) {
        w4 = ((const float4*)wt)[lane];
        b4 = ((const float4*)bt)[lane];
    }

    const float4 z = make_float4(0.f, 0.f, 0.f, 0.f);
    float4 av = z, A0 = z, A1 = z;
    float den0 = 0.f, den1 = 0.f;

    int nit = (deg + 1) >> 1;

    float relA = 0.f, relB = 0.f;
    float4 kkA = z, vvA = z, mgA = z, kkB = z, vvB = z, mgB = z;
    bool vB = false;

    auto loadE = [&](int idx, float& rel, float4& kk, float4& vv, float4& mg) {
        float4 p = g_epack[off + idx];
        int s = __float_as_int(p.x), e = __float_as_int(p.y);
        rel = p.z;
        const float4* KV4 = (const float4*)(g_KV + (size_t)s * 256);
        kk = KV4[lane]; vv = KV4[32 + lane];
        if (lane >= 16) mg = ((const float4*)(msg + (size_t)e * 64))[lane - 16];
    };

    if (deg > 0) {
        loadE(0, relA, kkA, vvA, mgA);
        vB = (1 < deg);
        if (vB) loadE(1, relB, kkB, vvB, mgB);
    }

    for (int it = 0; it < nit; it++) {
        // prefetch next pair
        float relA2 = 0.f, relB2 = 0.f;
        float4 kkA2 = z, vvA2 = z, mgA2 = z, kkB2 = z, vvB2 = z, mgB2 = z;
        bool vB2 = false;
        if (it + 1 < nit) {
            int idx = 2 * (it + 1);
            loadE(idx, relA2, kkA2, vvA2, mgA2);
            vB2 = (idx + 1 < deg);
            if (vB2) loadE(idx + 1, relB2, kkB2, vvB2, mgB2);
        }

        float4 eaA, eaB;
        if (lane < 16) {
            eaA.x = coss(fmaf(relA, w4.x, b4.x));
            eaA.y = coss(fmaf(relA, w4.y, b4.y));
            eaA.z = coss(fmaf(relA, w4.z, b4.z));
            eaA.w = coss(fmaf(relA, w4.w, b4.w));
            eaB.x = coss(fmaf(relB, w4.x, b4.x));
            eaB.y = coss(fmaf(relB, w4.y, b4.y));
            eaB.z = coss(fmaf(relB, w4.z, b4.z));
            eaB.w = coss(fmaf(relB, w4.w, b4.w));
        } else {
            eaA = mgA; eaB = mgB;
        }

        float pqkA = dot4(q4, kkA);
        float pqkB = dot4(q4, kkB);
        float s0A = dot4(eaA, u0) + (lane < 16 ? pqkA : 0.f);
        float s1A = dot4(eaA, u1) + (lane < 16 ? 0.f : pqkA);
        float s0B = dot4(eaB, u0) + (lane < 16 ? pqkB : 0.f);
        float s1B = dot4(eaB, u1) + (lane < 16 ? 0.f : pqkB);
#pragma unroll
        for (int o = 16; o; o >>= 1) {
            s0A += __shfl_xor_sync(0xffffffffu, s0A, o);
            s1A += __shfl_xor_sync(0xffffffffu, s1A, o);
            s0B += __shfl_xor_sync(0xffffffffu, s0B, o);
            s1B += __shfl_xor_sync(0xffffffffu, s1B, o);
        }

        float ex0A = __expf(s0A * 0.125f);
        float ex1A = __expf(s1A * 0.125f);
        float ex0B = vB ? __expf(s0B * 0.125f) : 0.f;
        float ex1B = vB ? __expf(s1B * 0.125f) : 0.f;
        den0 += ex0A + ex0B;
        den1 += ex1A + ex1B;

        float evA = (lane < 16) ? ex0A : ex1A;
        float evB = (lane < 16) ? ex0B : ex1B;
        av = fma4(evA, vvA, av);
        av = fma4(evB, vvB, av);
        A0 = fma4(ex0A, eaA, A0);
        A0 = fma4(ex0B, eaB, A0);
        A1 = fma4(ex1A, eaA, A1);
        A1 = fma4(ex1B, eaB, A1);

        relA = relA2; kkA = kkA2; vvA = vvA2; mgA = mgA2;
        relB = relB2; kkB = kkB2; vvB = vvB2; mgB = mgB2;
        vB = vB2;
    }

    float inv0 = 1.f / (den0 + 1e-16f);
    float inv1 = 1.f / (den1 + 1e-16f);
    float invv = (lane < 16) ? inv0 : inv1;

    float4* op = ((float4*)out) + (size_t)n * 32 + lane;
    float4 o = *op;
    o.x += av.x * invv; o.y += av.y * invv;
    o.z += av.z * invv; o.w += av.w * invv;
    *op = o;

    __half2* acc2 = (__half2*)(g_acch + (size_t)n * 256);
    acc2[2 * lane + 0]  = __float22half2_rn(make_float2(A0.x * inv0, A0.y * inv0));
    acc2[2 * lane + 1]  = __float22half2_rn(make_float2(A0.z * inv0, A0.w * inv0));
    acc2[64 + 2 * lane] = __float22half2_rn(make_float2(A1.x * inv1, A1.y * inv1));
    acc2[65 + 2 * lane] = __float22half2_rn(make_float2(A1.z * inv1, A1.w * inv1));
}

// ---------------------------------------------------------------------------
extern "C" void kernel_launch(void* const* d_in, const int* in_sizes, int n_in,
                              void* d_out, int out_size)
{
    const float* x    = (const float*)d_in[0];
    const float* lu   = (const float*)d_in[1];
    const int*   ei   = (const int*)  d_in[2];
    const float* tt   = (const float*)d_in[3];
    const float* msg  = (const float*)d_in[4];
    const float* wt   = (const float*)d_in[5];
    const float* bt   = (const float*)d_in[6];
    const float* Wq   = (const float*)d_in[7];
    const float* bq   = (const float*)d_in[8];
    const float* Wk   = (const float*)d_in[9];
    const float* bk   = (const float*)d_in[10];
    const float* Wv   = (const float*)d_in[11];
    const float* bv   = (const float*)d_in[12];
    const float* We   = (const float*)d_in[13];
    const float* Ws   = (const float*)d_in[14];
    const float* bs   = (const float*)d_in[15];
    float* out = (float*)d_out;

    int N = in_sizes[1];
    int E = in_sizes[3];

    float* pbcat;
    __half *pxh, *pBcatTh, *pBblkTh, *pacch;
    cudaGetSymbolAddress((void**)&pbcat,   g_bcat);
    cudaGetSymbolAddress((void**)&pxh,     g_xh);
    cudaGetSymbolAddress((void**)&pBcatTh, g_BcatTh);
    cudaGetSymbolAddress((void**)&pBblkTh, g_BblkTh);
    cudaGetSymbolAddress((void**)&pacch,   g_acch);

    int gm = (N + 127) / 128;
    int nb = (N + 511) / 512;

    prep_k<<<896, 128>>>(Wq, bq, Wk, bk, Wv, bv, Ws, bs, We, N);      // 0
    convx_k<<<(N * 32 + 255) / 256, 256>>>(x, N * 32);                // 1
    hist_k<<<(E + 255) / 256, 256>>>(ei, E);                          // 2
    // Projection (fp16 mma + ldmatrix): index 3 = profiled slot
    mma_gemm_h<<<dim3(gm, 6), 256>>>(pxh, 128, pBcatTh, 128, out,     // 3
                                     N, 128, pbcat, 0, 1);
    scan1_k<<<nb, 512>>>(N);                                          // 4
    scan2_k<<<1, 256>>>(nb);                                          // 5
    scatter_k<<<(E + 255) / 256, 256>>>(ei, lu, tt, E);               // 6
    // Aggregation (warp per dst, 2 edges/iter), adds v-part into out
    agg_k<<<N, 32>>>(msg, wt, bt, out, N);                            // 7
    // Epilogue (fp16 mma): out += accE[N x 256] @ Bblk[256 x 128]
    mma_gemm_h<<<dim3(gm, 1), 256>>>(pacch, 256, pBblkTh, 256, out,   // 8
                                     N, 256, nullptr, 1, 0);
}

// round 16
// speedup vs baseline: 1.1957x; 1.1957x over previous
#include <cuda_runtime.h>
#include <cuda_fp16.h>
#include <math.h>
#include <stdint.h>

#define MAX_N 100000
#define MAX_E 600000

__device__ float  g_QU  [(size_t)MAX_N * 384];  // q(128)|u0(128)|u1(128) fp32
__device__ float  g_KV  [(size_t)MAX_N * 256];  // k(128)|v(128) fp32
__device__ __half g_xh  [(size_t)MAX_N * 128];  // x in fp16
__device__ __half g_acch[(size_t)MAX_N * 256];  // normalized e-accumulators, fp16
__device__ __half g_BcatTh[768 * 128];          // [n][k] fp16
__device__ float  g_bcat[768];
__device__ __half g_BblkTh[128 * 256];          // [n][k] fp16
__device__ int    g_cnt[MAX_N];
__device__ int    g_off[MAX_N];
__device__ int    g_cur[MAX_N];
__device__ int    g_bsum[256];
__device__ float4 g_epack[MAX_E];               // (src_bits, e_bits, relt, 0) grouped by dst

// ---------------------------------------------------------------------------
// PTX helpers
// ---------------------------------------------------------------------------
__device__ __forceinline__ void cpz(unsigned dst, const void* src, int sz) {
    asm volatile("cp.async.cg.shared.global [%0], [%1], 16, %2;"
                 :: "r"(dst), "l"(src), "r"(sz));
}
__device__ __forceinline__ void mma16h(float* c, const uint32_t* a, const uint32_t* b) {
    asm volatile("mma.sync.aligned.m16n8k16.row.col.f32.f16.f16.f32 "
        "{%0,%1,%2,%3}, {%4,%5,%6,%7}, {%8,%9}, {%0,%1,%2,%3};"
        : "+f"(c[0]), "+f"(c[1]), "+f"(c[2]), "+f"(c[3])
        : "r"(a[0]), "r"(a[1]), "r"(a[2]), "r"(a[3]), "r"(b[0]), "r"(b[1]));
}
__device__ __forceinline__ void ldsm4(uint32_t& r0, uint32_t& r1,
                                      uint32_t& r2, uint32_t& r3, uint32_t addr) {
    asm volatile("ldmatrix.sync.aligned.m8n8.x4.shared.b16 {%0,%1,%2,%3}, [%4];"
        : "=r"(r0), "=r"(r1), "=r"(r2), "=r"(r3) : "r"(addr));
}

// ---------------------------------------------------------------------------
// fp16 GEMM with ldmatrix fragment loads (R14-proven).
// C[M x (128*gridDim.y)] = A[M x K] @ B (+bias)(+=C), fp32 accum.
// BM=128, BN=128, BK=32, 256 thr (8 warps, 4x2), warp tile 64x64, m16n8k16.
// ---------------------------------------------------------------------------
__global__ __launch_bounds__(256) void mma_gemm_h(
    const __half* __restrict__ A, int lda,
    const __half* __restrict__ BT, int ldb,
    float* __restrict__ C,
    int M, int K,
    const float* __restrict__ bias, int accum, int mode)
{
    __shared__ __half As[2][128][40];
    __shared__ __half Bs[2][128][40];
    const int tid = threadIdx.x;
    const int lane = tid & 31;
    const int warp = tid >> 5;
    const int wm = warp & 3, wn = warp >> 2;
    const int grp = lane >> 2, qd = lane & 3;
    const int bm0 = blockIdx.x * 128;
    const int bn0 = blockIdx.y * 128;

    const uint32_t asB = (uint32_t)__cvta_generic_to_shared(&As[0][0][0]);
    const uint32_t bsB = (uint32_t)__cvta_generic_to_shared(&Bs[0][0][0]);
    const int a_row = (lane & 7) + ((lane >> 3) & 1) * 8;
    const int a_koff = (lane >> 4) * 8;
    const int b_row = lane & 7;
    const int b_ntoff = (lane >> 4);
    const int b_koff = ((lane >> 3) & 1) * 8;

    float c[2][8][4];
#pragma unroll
    for (int i = 0; i < 2; i++)
#pragma unroll
        for (int j = 0; j < 8; j++)
#pragma unroll
            for (int u = 0; u < 4; u++) c[i][j][u] = 0.f;

    const int ntiles = K >> 5;   // BK=32

    auto cpA = [&](int kt, int buf) {
#pragma unroll
        for (int it = 0; it < 2; it++) {
            int idx = tid + 256 * it;
            int row = idx >> 2, ch = (idx & 3) * 8;
            int gr = bm0 + row;
            int grc = gr < M ? gr : (M - 1);
            const __half* src = A + (size_t)grc * lda + kt * 32 + ch;
            unsigned dst = (unsigned)__cvta_generic_to_shared(&As[buf][row][ch]);
            cpz(dst, src, gr < M ? 16 : 0);
        }
    };
    auto cpB = [&](int kt, int buf) {
#pragma unroll
        for (int it = 0; it < 2; it++) {
            int idx = tid + 256 * it;
            int row = idx >> 2, ch = (idx & 3) * 8;
            const __half* src = BT + (size_t)(bn0 + row) * ldb + kt * 32 + ch;
            unsigned dst = (unsigned)__cvta_generic_to_shared(&Bs[buf][row][ch]);
            cpz(dst, src, 16);
        }
    };

    cpA(0, 0); cpB(0, 0);
    asm volatile("cp.async.commit_group;");
    asm volatile("cp.async.wait_group 0;");
    __syncthreads();

    for (int t = 0; t < ntiles; t++) {
        int cur = t & 1, nxt = cur ^ 1;
        bool more = (t + 1 < ntiles);
        if (more) {
            cpA(t + 1, nxt); cpB(t + 1, nxt);
            asm volatile("cp.async.commit_group;");
        }
        uint32_t aOff = asB + cur * 10240;
        uint32_t bOff = bsB + cur * 10240;
#pragma unroll
        for (int kk = 0; kk < 2; kk++) {        // two k16 steps per slab
            int k0 = kk * 16;
            uint32_t af[2][4], bf[8][2];
#pragma unroll
            for (int mt = 0; mt < 2; mt++) {
                uint32_t addr = aOff + (uint32_t)(wm * 32 + mt * 16 + a_row) * 80
                              + (uint32_t)(k0 + a_koff) * 2;
                ldsm4(af[mt][0], af[mt][1], af[mt][2], af[mt][3], addr);
            }
#pragma unroll
            for (int p = 0; p < 4; p++) {       // nt pairs (2p, 2p+1)
                uint32_t addr = bOff + (uint32_t)(wn * 64 + (2 * p + b_ntoff) * 8 + b_row) * 80
                              + (uint32_t)(k0 + b_koff) * 2;
                ldsm4(bf[2 * p][0], bf[2 * p][1], bf[2 * p + 1][0], bf[2 * p + 1][1], addr);
            }
#pragma unroll
            for (int mt = 0; mt < 2; mt++)
#pragma unroll
                for (int nt = 0; nt < 8; nt++)
                    mma16h(c[mt][nt], af[mt], bf[nt]);
        }
        if (more) asm volatile("cp.async.wait_group 0;");
        __syncthreads();
    }

    // Uniform store-target selection (per block)
    float* baseP; int ldo, csub;
    if (mode == 0)      { baseP = C;     ldo = 128; csub = 0;   }
    else if (bn0 < 384) { baseP = g_QU;  ldo = 384; csub = 0;   }
    else if (bn0 < 640) { baseP = g_KV;  ldo = 256; csub = 384; }
    else                { baseP = C;     ldo = 128; csub = 640; }

#pragma unroll
    for (int mt = 0; mt < 2; mt++)
#pragma unroll
        for (int nt = 0; nt < 8; nt++)
#pragma unroll
            for (int hf = 0; hf < 2; hf++) {
                int row = bm0 + wm * 32 + mt * 16 + grp + hf * 8;
                if (row >= M) continue;
                int col = bn0 + wn * 64 + nt * 8 + qd * 2;
                float2 v2;
                v2.x = c[mt][nt][hf * 2 + 0];
                v2.y = c[mt][nt][hf * 2 + 1];
                if (bias) { v2.x += bias[col]; v2.y += bias[col + 1]; }
                float* cp = baseP + (size_t)row * ldo + (col - csub);
                if (accum) { v2.x += cp[0]; v2.y += cp[1]; }
                *(float2*)cp = v2;
            }
}

// ---------------------------------------------------------------------------
// x -> fp16 conversion
// ---------------------------------------------------------------------------
__global__ __launch_bounds__(256) void convx_k(const float* __restrict__ x, int total4)
{
    int i = blockIdx.x * 256 + threadIdx.x;
    if (i >= total4) return;
    float4 v = ((const float4*)x)[i];
    __half2* o = (__half2*)g_xh;
    o[2 * i + 0] = __float22half2_rn(make_float2(v.x, v.y));
    o[2 * i + 1] = __float22half2_rn(make_float2(v.z, v.w));
}

// ---------------------------------------------------------------------------
// Fused prep (fp16 weights). Zeroes g_cnt/g_cur.
// ---------------------------------------------------------------------------
__global__ __launch_bounds__(128) void prep_k(
    const float* __restrict__ Wq, const float* __restrict__ bq,
    const float* __restrict__ Wk, const float* __restrict__ bk,
    const float* __restrict__ Wv, const float* __restrict__ bv,
    const float* __restrict__ Ws, const float* __restrict__ bs,
    const float* __restrict__ We, int N)
{
    int j = blockIdx.x;
    int r = threadIdx.x;

    for (int i = j * 128 + r; i < N; i += 896 * 128) {
        g_cnt[i] = 0;
        g_cur[i] = 0;
    }

    if (j >= 768) {
        int n = j - 768;
#pragma unroll
        for (int kq = 0; kq < 2; kq++) {
            int k = r + kq * 128;
            float v = 0.f;
            if (k < 128) { if (n < 64)  v = We[k * 128 + n]; }
            else         { if (n >= 64) v = We[(k - 128) * 128 + n]; }
            g_BblkTh[n * 256 + k] = __float2half_rn(v);
        }
        return;
    }

    float v;
    if (j < 128) v = Wq[r * 128 + j];
    else if (j < 256) {
        int d = j - 128; const float* w = We + d * 128;
        float s = 0.f;
#pragma unroll
        for (int c = 0; c < 64; c++) s = fmaf(Wq[r * 128 + c], w[c], s);
        v = s;
    } else if (j < 384) {
        int d = j - 256; const float* w = We + d * 128 + 64;
        float s = 0.f;
#pragma unroll
        for (int c = 0; c < 64; c++) s = fmaf(Wq[r * 128 + 64 + c], w[c], s);
        v = s;
    }
    else if (j < 512) v = Wk[r * 128 + (j - 384)];
    else if (j < 640) v = Wv[r * 128 + (j - 512)];
    else              v = Ws[r * 128 + (j - 640)];
    g_BcatTh[j * 128 + r] = __float2half_rn(v);

    if (r == 0) {
        float bv2;
        if (j < 128) bv2 = bq[j];
        else if (j < 256) {
            int d = j - 128; const float* w = We + d * 128;
            float s = 0.f;
            for (int c = 0; c < 64; c++) s = fmaf(bq[c], w[c], s);
            bv2 = s;
        } else if (j < 384) {
            int d = j - 256; const float* w = We + d * 128 + 64;
            float s = 0.f;
            for (int c = 0; c < 64; c++) s = fmaf(bq[64 + c], w[c], s);
            bv2 = s;
        }
        else if (j < 512) bv2 = bk[j - 384];
        else if (j < 640) bv2 = bv[j - 512];
        else              bv2 = bs[j - 640];
        g_bcat[j] = bv2;
    }
}

// ---------------------------------------------------------------------------
// Edge binning (counting sort by dst)
// ---------------------------------------------------------------------------
__global__ __launch_bounds__(256) void hist_k(const int* __restrict__ ei, int E)
{
    int i = blockIdx.x * 256 + threadIdx.x;
    if (i < E) atomicAdd(&g_cnt[ei[E + i]], 1);
}

__global__ __launch_bounds__(512) void scan1_k(int N)
{
    __shared__ int sh[512];
    int tid = threadIdx.x;
    int i = blockIdx.x * 512 + tid;
    int v = (i < N) ? g_cnt[i] : 0;
    sh[tid] = v;
    __syncthreads();
#pragma unroll
    for (int o = 1; o < 512; o <<= 1) {
        int t = (tid >= o) ? sh[tid - o] : 0;
        __syncthreads();
        sh[tid] += t;
        __syncthreads();
    }
    if (i < N) g_off[i] = sh[tid] - v;
    if (tid == 511) g_bsum[blockIdx.x] = sh[511];
}

__global__ __launch_bounds__(256) void scan2_k(int nb)
{
    __shared__ int sh[256];
    int tid = threadIdx.x;
    int v = (tid < nb) ? g_bsum[tid] : 0;
    sh[tid] = v;
    __syncthreads();
#pragma unroll
    for (int o = 1; o < 256; o <<= 1) {
        int t = (tid >= o) ? sh[tid - o] : 0;
        __syncthreads();
        sh[tid] += t;
        __syncthreads();
    }
    if (tid < nb) g_bsum[tid] = sh[tid] - v;
}

__global__ __launch_bounds__(256) void scatter_k(
    const int* __restrict__ ei, const float* __restrict__ lu,
    const float* __restrict__ tt, int E)
{
    int e = blockIdx.x * 256 + threadIdx.x;
    if (e >= E) return;
    int src = ei[e];
    int dst = ei[E + e];
    int base = g_off[dst] + g_bsum[dst >> 9];
    int pos = base + atomicAdd(&g_cur[dst], 1);
    float4 p;
    p.x = __int_as_float(src);
    p.y = __int_as_float(e);
    p.z = lu[src] - tt[e];
    p.w = 0.f;
    g_epack[pos] = p;
}

// ---------------------------------------------------------------------------
// Aggregation: one warp per dst node, 32-thread blocks, packed edge records
// (R13-proven single-edge loop — wider ILP variants regress).
// ---------------------------------------------------------------------------
__device__ __forceinline__ float coss(float x) {
    float k = rintf(x * 0.15915494309189535f);
    float r = fmaf(k, -6.28125f, x);
    r = fmaf(k, -1.93530717958623e-3f, r);
    return __cosf(r);
}
__device__ __forceinline__ float dot4(float4 a, float4 b) {
    return a.x * b.x + a.y * b.y + a.z * b.z + a.w * b.w;
}
__device__ __forceinline__ float4 fma4(float s, float4 a, float4 acc) {
    acc.x = fmaf(s, a.x, acc.x);
    acc.y = fmaf(s, a.y, acc.y);
    acc.z = fmaf(s, a.z, acc.z);
    acc.w = fmaf(s, a.w, acc.w);
    return acc;
}

__global__ __launch_bounds__(32) void agg_k(
    const float* __restrict__ msg,
    const float* __restrict__ wt, const float* __restrict__ bt,
    float* __restrict__ out, int N)
{
    int n = blockIdx.x;
    int lane = threadIdx.x;
    if (n >= N) return;

    int off = g_off[n] + g_bsum[n >> 9];
    int deg = g_cnt[n];

    const float4* QU4 = (const float4*)(g_QU + (size_t)n * 384);
    float4 q4 = QU4[lane];
    float4 u0 = QU4[32 + lane];
    float4 u1 = QU4[64 + lane];

    float4 w4 = make_float4(0.f, 0.f, 0.f, 0.f), b4 = w4;
    if (lane < 16) {
        w4 = ((const float4*)wt)[lane];
        b4 = ((const float4*)bt)[lane];
    }

    float4 av = make_float4(0.f, 0.f, 0.f, 0.f);
    float4 A0 = av, A1 = av;
    float den0 = 0.f, den1 = 0.f;

    int srcc = 0, ec = 0;
    float rel = 0.f;
    float4 kk = av, vv = av, mg = av;
    if (deg > 0) {
        float4 p = g_epack[off];
        srcc = __float_as_int(p.x); ec = __float_as_int(p.y); rel = p.z;
        const float4* KV4 = (const float4*)(g_KV + (size_t)srcc * 256);
        kk = KV4[lane]; vv = KV4[32 + lane];
        if (lane >= 16) mg = ((const float4*)(msg + (size_t)ec * 64))[lane - 16];
    }

    for (int i = 0; i < deg; i++) {
        int src2 = srcc, e2 = ec; float rel2 = 0.f;
        float4 kk2 = av, vv2 = av, mg2 = av;
        bool more = (i + 1 < deg);
        if (more) {
            float4 p = g_epack[off + i + 1];
            src2 = __float_as_int(p.x); e2 = __float_as_int(p.y); rel2 = p.z;
            const float4* KV4 = (const float4*)(g_KV + (size_t)src2 * 256);
            kk2 = KV4[lane]; vv2 = KV4[32 + lane];
            if (lane >= 16) mg2 = ((const float4*)(msg + (size_t)e2 * 64))[lane - 16];
        }

        float4 ea;
        if (lane < 16) {
            ea.x = coss(fmaf(rel, w4.x, b4.x));
            ea.y = coss(fmaf(rel, w4.y, b4.y));
            ea.z = coss(fmaf(rel, w4.z, b4.z));
            ea.w = coss(fmaf(rel, w4.w, b4.w));
        } else {
            ea = mg;
        }

        float pqk = dot4(q4, kk);
        float s0 = dot4(ea, u0) + (lane < 16 ? pqk : 0.f);
        float s1 = dot4(ea, u1) + (lane < 16 ? 0.f : pqk);
#pragma unroll
        for (int o = 16; o; o >>= 1) {
            s0 += __shfl_xor_sync(0xffffffffu, s0, o);
            s1 += __shfl_xor_sync(0xffffffffu, s1, o);
        }

        float ex0 = __expf(s0 * 0.125f);
        float ex1 = __expf(s1 * 0.125f);
        den0 += ex0;
        den1 += ex1;

        float evv = (lane < 16) ? ex0 : ex1;
        av = fma4(evv, vv, av);
        A0 = fma4(ex0, ea, A0);
        A1 = fma4(ex1, ea, A1);

        srcc = src2; ec = e2; rel = rel2; kk = kk2; vv = vv2; mg = mg2;
    }

    float inv0 = 1.f / (den0 + 1e-16f);
    float inv1 = 1.f / (den1 + 1e-16f);
    float invv = (lane < 16) ? inv0 : inv1;

    float4* op = ((float4*)out) + (size_t)n * 32 + lane;
    float4 o = *op;
    o.x += av.x * invv; o.y += av.y * invv;
    o.z += av.z * invv; o.w += av.w * invv;
    *op = o;

    // store e-accumulators as fp16 (epilogue fp16 GEMM operand)
    __half2* acc2 = (__half2*)(g_acch + (size_t)n * 256);
    acc2[2 * lane + 0]  = __float22half2_rn(make_float2(A0.x * inv0, A0.y * inv0));
    acc2[2 * lane + 1]  = __float22half2_rn(make_float2(A0.z * inv0, A0.w * inv0));
    acc2[64 + 2 * lane] = __float22half2_rn(make_float2(A1.x * inv1, A1.y * inv1));
    acc2[65 + 2 * lane] = __float22half2_rn(make_float2(A1.z * inv1, A1.w * inv1));
}

// ---------------------------------------------------------------------------
extern "C" void kernel_launch(void* const* d_in, const int* in_sizes, int n_in,
                              void* d_out, int out_size)
{
    const float* x    = (const float*)d_in[0];
    const float* lu   = (const float*)d_in[1];
    const int*   ei   = (const int*)  d_in[2];
    const float* tt   = (const float*)d_in[3];
    const float* msg  = (const float*)d_in[4];
    const float* wt   = (const float*)d_in[5];
    const float* bt   = (const float*)d_in[6];
    const float* Wq   = (const float*)d_in[7];
    const float* bq   = (const float*)d_in[8];
    const float* Wk   = (const float*)d_in[9];
    const float* bk   = (const float*)d_in[10];
    const float* Wv   = (const float*)d_in[11];
    const float* bv   = (const float*)d_in[12];
    const float* We   = (const float*)d_in[13];
    const float* Ws   = (const float*)d_in[14];
    const float* bs   = (const float*)d_in[15];
    float* out = (float*)d_out;

    int N = in_sizes[1];
    int E = in_sizes[3];

    float* pbcat;
    __half *pxh, *pBcatTh, *pBblkTh, *pacch;
    cudaGetSymbolAddress((void**)&pbcat,   g_bcat);
    cudaGetSymbolAddress((void**)&pxh,     g_xh);
    cudaGetSymbolAddress((void**)&pBcatTh, g_BcatTh);
    cudaGetSymbolAddress((void**)&pBblkTh, g_BblkTh);
    cudaGetSymbolAddress((void**)&pacch,   g_acch);

    int gm = (N + 127) / 128;
    int nb = (N + 511) / 512;

    prep_k<<<896, 128>>>(Wq, bq, Wk, bk, Wv, bv, Ws, bs, We, N);      // 0
    convx_k<<<(N * 32 + 255) / 256, 256>>>(x, N * 32);                // 1
    hist_k<<<(E + 255) / 256, 256>>>(ei, E);                          // 2
    // Projection (fp16 mma + ldmatrix): index 3 = profiled slot
    mma_gemm_h<<<dim3(gm, 6), 256>>>(pxh, 128, pBcatTh, 128, out,     // 3
                                     N, 128, pbcat, 0, 1);
    scan1_k<<<nb, 512>>>(N);                                          // 4
    scan2_k<<<1, 256>>>(nb);                                          // 5
    scatter_k<<<(E + 255) / 256, 256>>>(ei, lu, tt, E);               // 6
    // Aggregation (1 warp per dst node), adds v-part into out
    agg_k<<<N, 32>>>(msg, wt, bt, out, N);                            // 7
    // Epilogue (fp16 mma): out += accE[N x 256] @ Bblk[256 x 128]
    mma_gemm_h<<<dim3(gm, 1), 256>>>(pacch, 256, pBblkTh, 256, out,   // 8
                                     N, 256, nullptr, 1, 0);
}

// round 17
// speedup vs baseline: 1.2631x; 1.0563x over previous
#include <cuda_runtime.h>
#include <cuda_fp16.h>
#include <math.h>
#include <stdint.h>

#define MAX_N 100000
#define MAX_E 600000
#define DSTG 4

__device__ float  g_QU  [(size_t)MAX_N * 384];  // q(128)|u0(128)|u1(128) fp32
__device__ float  g_KV  [(size_t)MAX_N * 256];  // k(128)|v(128) fp32
__device__ __half g_xh  [(size_t)MAX_N * 128];  // x in fp16
__device__ __half g_acch[(size_t)MAX_N * 256];  // normalized e-accumulators, fp16
__device__ __half g_BcatTh[768 * 128];          // [n][k] fp16
__device__ float  g_bcat[768];
__device__ __half g_BblkTh[128 * 256];          // [n][k] fp16
__device__ int    g_cnt[MAX_N];
__device__ int    g_off[MAX_N];
__device__ int    g_cur[MAX_N];
__device__ int    g_bsum[256];
__device__ float4 g_epack[MAX_E];               // (src_bits, e_bits, relt, 0) grouped by dst

// ---------------------------------------------------------------------------
// PTX helpers
// ---------------------------------------------------------------------------
__device__ __forceinline__ void cpz(unsigned dst, const void* src, int sz) {
    asm volatile("cp.async.cg.shared.global [%0], [%1], 16, %2;"
                 :: "r"(dst), "l"(src), "r"(sz));
}
__device__ __forceinline__ void cp16(unsigned dst, const void* src) {
    asm volatile("cp.async.cg.shared.global [%0], [%1], 16;"
                 :: "r"(dst), "l"(src) : "memory");
}
__device__ __forceinline__ void mma16h(float* c, const uint32_t* a, const uint32_t* b) {
    asm volatile("mma.sync.aligned.m16n8k16.row.col.f32.f16.f16.f32 "
        "{%0,%1,%2,%3}, {%4,%5,%6,%7}, {%8,%9}, {%0,%1,%2,%3};"
        : "+f"(c[0]), "+f"(c[1]), "+f"(c[2]), "+f"(c[3])
        : "r"(a[0]), "r"(a[1]), "r"(a[2]), "r"(a[3]), "r"(b[0]), "r"(b[1]));
}
__device__ __forceinline__ void ldsm4(uint32_t& r0, uint32_t& r1,
                                      uint32_t& r2, uint32_t& r3, uint32_t addr) {
    asm volatile("ldmatrix.sync.aligned.m8n8.x4.shared.b16 {%0,%1,%2,%3}, [%4];"
        : "=r"(r0), "=r"(r1), "=r"(r2), "=r"(r3) : "r"(addr));
}

// ---------------------------------------------------------------------------
// fp16 GEMM with ldmatrix fragment loads (R16-proven).
// ---------------------------------------------------------------------------
__global__ __launch_bounds__(256) void mma_gemm_h(
    const __half* __restrict__ A, int lda,
    const __half* __restrict__ BT, int ldb,
    float* __restrict__ C,
    int M, int K,
    const float* __restrict__ bias, int accum, int mode)
{
    __shared__ __half As[2][128][40];
    __shared__ __half Bs[2][128][40];
    const int tid = threadIdx.x;
    const int lane = tid & 31;
    const int warp = tid >> 5;
    const int wm = warp & 3, wn = warp >> 2;
    const int grp = lane >> 2, qd = lane & 3;
    const int bm0 = blockIdx.x * 128;
    const int bn0 = blockIdx.y * 128;

    const uint32_t asB = (uint32_t)__cvta_generic_to_shared(&As[0][0][0]);
    const uint32_t bsB = (uint32_t)__cvta_generic_to_shared(&Bs[0][0][0]);
    const int a_row = (lane & 7) + ((lane >> 3) & 1) * 8;
    const int a_koff = (lane >> 4) * 8;
    const int b_row = lane & 7;
    const int b_ntoff = (lane >> 4);
    const int b_koff = ((lane >> 3) & 1) * 8;

    float c[2][8][4];
#pragma unroll
    for (int i = 0; i < 2; i++)
#pragma unroll
        for (int j = 0; j < 8; j++)
#pragma unroll
            for (int u = 0; u < 4; u++) c[i][j][u] = 0.f;

    const int ntiles = K >> 5;   // BK=32

    auto cpA = [&](int kt, int buf) {
#pragma unroll
        for (int it = 0; it < 2; it++) {
            int idx = tid + 256 * it;
            int row = idx >> 2, ch = (idx & 3) * 8;
            int gr = bm0 + row;
            int grc = gr < M ? gr : (M - 1);
            const __half* src = A + (size_t)grc * lda + kt * 32 + ch;
            unsigned dst = (unsigned)__cvta_generic_to_shared(&As[buf][row][ch]);
            cpz(dst, src, gr < M ? 16 : 0);
        }
    };
    auto cpB = [&](int kt, int buf) {
#pragma unroll
        for (int it = 0; it < 2; it++) {
            int idx = tid + 256 * it;
            int row = idx >> 2, ch = (idx & 3) * 8;
            const __half* src = BT + (size_t)(bn0 + row) * ldb + kt * 32 + ch;
            unsigned dst = (unsigned)__cvta_generic_to_shared(&Bs[buf][row][ch]);
            cpz(dst, src, 16);
        }
    };

    cpA(0, 0); cpB(0, 0);
    asm volatile("cp.async.commit_group;");
    asm volatile("cp.async.wait_group 0;");
    __syncthreads();

    for (int t = 0; t < ntiles; t++) {
        int cur = t & 1, nxt = cur ^ 1;
        bool more = (t + 1 < ntiles);
        if (more) {
            cpA(t + 1, nxt); cpB(t + 1, nxt);
            asm volatile("cp.async.commit_group;");
        }
        uint32_t aOff = asB + cur * 10240;
        uint32_t bOff = bsB + cur * 10240;
#pragma unroll
        for (int kk = 0; kk < 2; kk++) {
            int k0 = kk * 16;
            uint32_t af[2][4], bf[8][2];
#pragma unroll
            for (int mt = 0; mt < 2; mt++) {
                uint32_t addr = aOff + (uint32_t)(wm * 32 + mt * 16 + a_row) * 80
                              + (uint32_t)(k0 + a_koff) * 2;
                ldsm4(af[mt][0], af[mt][1], af[mt][2], af[mt][3], addr);
            }
#pragma unroll
            for (int p = 0; p < 4; p++) {
                uint32_t addr = bOff + (uint32_t)(wn * 64 + (2 * p + b_ntoff) * 8 + b_row) * 80
                              + (uint32_t)(k0 + b_koff) * 2;
                ldsm4(bf[2 * p][0], bf[2 * p][1], bf[2 * p + 1][0], bf[2 * p + 1][1], addr);
            }
#pragma unroll
            for (int mt = 0; mt < 2; mt++)
#pragma unroll
                for (int nt = 0; nt < 8; nt++)
                    mma16h(c[mt][nt], af[mt], bf[nt]);
        }
        if (more) asm volatile("cp.async.wait_group 0;");
        __syncthreads();
    }

    float* baseP; int ldo, csub;
    if (mode == 0)      { baseP = C;     ldo = 128; csub = 0;   }
    else if (bn0 < 384) { baseP = g_QU;  ldo = 384; csub = 0;   }
    else if (bn0 < 640) { baseP = g_KV;  ldo = 256; csub = 384; }
    else                { baseP = C;     ldo = 128; csub = 640; }

#pragma unroll
    for (int mt = 0; mt < 2; mt++)
#pragma unroll
        for (int nt = 0; nt < 8; nt++)
#pragma unroll
            for (int hf = 0; hf < 2; hf++) {
                int row = bm0 + wm * 32 + mt * 16 + grp + hf * 8;
                if (row >= M) continue;
                int col = bn0 + wn * 64 + nt * 8 + qd * 2;
                float2 v2;
                v2.x = c[mt][nt][hf * 2 + 0];
                v2.y = c[mt][nt][hf * 2 + 1];
                if (bias) { v2.x += bias[col]; v2.y += bias[col + 1]; }
                float* cp = baseP + (size_t)row * ldo + (col - csub);
                if (accum) { v2.x += cp[0]; v2.y += cp[1]; }
                *(float2*)cp = v2;
            }
}

// ---------------------------------------------------------------------------
// x -> fp16 conversion
// ---------------------------------------------------------------------------
__global__ __launch_bounds__(256) void convx_k(const float* __restrict__ x, int total4)
{
    int i = blockIdx.x * 256 + threadIdx.x;
    if (i >= total4) return;
    float4 v = ((const float4*)x)[i];
    __half2* o = (__half2*)g_xh;
    o[2 * i + 0] = __float22half2_rn(make_float2(v.x, v.y));
    o[2 * i + 1] = __float22half2_rn(make_float2(v.z, v.w));
}

// ---------------------------------------------------------------------------
// Fused prep (fp16 weights). Zeroes g_cnt/g_cur.
// ---------------------------------------------------------------------------
__global__ __launch_bounds__(128) void prep_k(
    const float* __restrict__ Wq, const float* __restrict__ bq,
    const float* __restrict__ Wk, const float* __restrict__ bk,
    const float* __restrict__ Wv, const float* __restrict__ bv,
    const float* __restrict__ Ws, const float* __restrict__ bs,
    const float* __restrict__ We, int N)
{
    int j = blockIdx.x;
    int r = threadIdx.x;

    for (int i = j * 128 + r; i < N; i += 896 * 128) {
        g_cnt[i] = 0;
        g_cur[i] = 0;
    }

    if (j >= 768) {
        int n = j - 768;
#pragma unroll
        for (int kq = 0; kq < 2; kq++) {
            int k = r + kq * 128;
            float v = 0.f;
            if (k < 128) { if (n < 64)  v = We[k * 128 + n]; }
            else         { if (n >= 64) v = We[(k - 128) * 128 + n]; }
            g_BblkTh[n * 256 + k] = __float2half_rn(v);
        }
        return;
    }

    float v;
    if (j < 128) v = Wq[r * 128 + j];
    else if (j < 256) {
        int d = j - 128; const float* w = We + d * 128;
        float s = 0.f;
#pragma unroll
        for (int c = 0; c < 64; c++) s = fmaf(Wq[r * 128 + c], w[c], s);
        v = s;
    } else if (j < 384) {
        int d = j - 256; const float* w = We + d * 128 + 64;
        float s = 0.f;
#pragma unroll
        for (int c = 0; c < 64; c++) s = fmaf(Wq[r * 128 + 64 + c], w[c], s);
        v = s;
    }
    else if (j < 512) v = Wk[r * 128 + (j - 384)];
    else if (j < 640) v = Wv[r * 128 + (j - 512)];
    else              v = Ws[r * 128 + (j - 640)];
    g_BcatTh[j * 128 + r] = __float2half_rn(v);

    if (r == 0) {
        float bv2;
        if (j < 128) bv2 = bq[j];
        else if (j < 256) {
            int d = j - 128; const float* w = We + d * 128;
            float s = 0.f;
            for (int c = 0; c < 64; c++) s = fmaf(bq[c], w[c], s);
            bv2 = s;
        } else if (j < 384) {
            int d = j - 256; const float* w = We + d * 128 + 64;
            float s = 0.f;
            for (int c = 0; c < 64; c++) s = fmaf(bq[64 + c], w[c], s);
            bv2 = s;
        }
        else if (j < 512) bv2 = bk[j - 384];
        else if (j < 640) bv2 = bv[j - 512];
        else              bv2 = bs[j - 640];
        g_bcat[j] = bv2;
    }
}

// ---------------------------------------------------------------------------
// Edge binning (counting sort by dst)
// ---------------------------------------------------------------------------
__global__ __launch_bounds__(256) void hist_k(const int* __restrict__ ei, int E)
{
    int i = blockIdx.x * 256 + threadIdx.x;
    if (i < E) atomicAdd(&g_cnt[ei[E + i]], 1);
}

__global__ __launch_bounds__(512) void scan1_k(int N)
{
    __shared__ int sh[512];
    int tid = threadIdx.x;
    int i = blockIdx.x * 512 + tid;
    int v = (i < N) ? g_cnt[i] : 0;
    sh[tid] = v;
    __syncthreads();
#pragma unroll
    for (int o = 1; o < 512; o <<= 1) {
        int t = (tid >= o) ? sh[tid - o] : 0;
        __syncthreads();
        sh[tid] += t;
        __syncthreads();
    }
    if (i < N) g_off[i] = sh[tid] - v;
    if (tid == 511) g_bsum[blockIdx.x] = sh[511];
}

__global__ __launch_bounds__(256) void scan2_k(int nb)
{
    __shared__ int sh[256];
    int tid = threadIdx.x;
    int v = (tid < nb) ? g_bsum[tid] : 0;
    sh[tid] = v;
    __syncthreads();
#pragma unroll
    for (int o = 1; o < 256; o <<= 1) {
        int t = (tid >= o) ? sh[tid - o] : 0;
        __syncthreads();
        sh[tid] += t;
        __syncthreads();
    }
    if (tid < nb) g_bsum[tid] = sh[tid] - v;
}

__global__ __launch_bounds__(256) void scatter_k(
    const int* __restrict__ ei, const float* __restrict__ lu,
    const float* __restrict__ tt, int E)
{
    int e = blockIdx.x * 256 + threadIdx.x;
    if (e >= E) return;
    int src = ei[e];
    int dst = ei[E + e];
    int base = g_off[dst] + g_bsum[dst >> 9];
    int pos = base + atomicAdd(&g_cur[dst], 1);
    float4 p;
    p.x = __int_as_float(src);
    p.y = __int_as_float(e);
    p.z = lu[src] - tt[e];
    p.w = 0.f;
    g_epack[pos] = p;
}

// ---------------------------------------------------------------------------
// Aggregation: one warp per dst node, DSTG-deep cp.async smem pipeline for
// KV/msg gathers (no staging registers -> no pressure).
// ---------------------------------------------------------------------------
__device__ __forceinline__ float coss(float x) {
    float k = rintf(x * 0.15915494309189535f);
    float r = fmaf(k, -6.28125f, x);
    r = fmaf(k, -1.93530717958623e-3f, r);
    return __cosf(r);
}
__device__ __forceinline__ float dot4(float4 a, float4 b) {
    return a.x * b.x + a.y * b.y + a.z * b.z + a.w * b.w;
}
__device__ __forceinline__ float4 fma4(float s, float4 a, float4 acc) {
    acc.x = fmaf(s, a.x, acc.x);
    acc.y = fmaf(s, a.y, acc.y);
    acc.z = fmaf(s, a.z, acc.z);
    acc.w = fmaf(s, a.w, acc.w);
    return acc;
}

__global__ __launch_bounds__(32) void agg_k(
    const float* __restrict__ msg,
    const float* __restrict__ wt, const float* __restrict__ bt,
    float* __restrict__ out, int N)
{
    __shared__ float4 sKV[DSTG][64];   // [slot][lane]=k, [slot][32+lane]=v
    __shared__ float4 sMG[DSTG][16];
    int n = blockIdx.x;
    int lane = threadIdx.x;
    if (n >= N) return;

    int off = g_off[n] + g_bsum[n >> 9];
    int deg = g_cnt[n];

    const float4* QU4 = (const float4*)(g_QU + (size_t)n * 384);
    float4 q4 = QU4[lane];
    float4 u0 = QU4[32 + lane];
    float4 u1 = QU4[64 + lane];

    float4 w4 = make_float4(0.f, 0.f, 0.f, 0.f), b4 = w4;
    if (lane < 16) {
        w4 = ((const float4*)wt)[lane];
        b4 = ((const float4*)bt)[lane];
    }

    float4 av = make_float4(0.f, 0.f, 0.f, 0.f);
    float4 A0 = av, A1 = av;
    float den0 = 0.f, den1 = 0.f;

    auto issue = [&](int j) {
        if (j < deg) {
            float4 p = g_epack[off + j];
            int s = __float_as_int(p.x);
            int e = __float_as_int(p.y);
            int slot = j & (DSTG - 1);
            const float4* KV4 = (const float4*)(g_KV + (size_t)s * 256);
            cp16((unsigned)__cvta_generic_to_shared(&sKV[slot][lane]), &KV4[lane]);
            cp16((unsigned)__cvta_generic_to_shared(&sKV[slot][32 + lane]), &KV4[32 + lane]);
            if (lane >= 16)
                cp16((unsigned)__cvta_generic_to_shared(&sMG[slot][lane - 16]),
                     ((const float4*)(msg + (size_t)e * 64)) + (lane - 16));
        }
        asm volatile("cp.async.commit_group;" ::: "memory");
    };

#pragma unroll
    for (int j = 0; j < DSTG; j++) issue(j);

    for (int i = 0; i < deg; i++) {
        asm volatile("cp.async.wait_group %0;" :: "n"(DSTG - 1) : "memory");
        __syncthreads();
        int slot = i & (DSTG - 1);
        float rel = g_epack[off + i].z;    // L1-hot reload (read at issue time)
        float4 kk = sKV[slot][lane];
        float4 vv = sKV[slot][32 + lane];
        float4 ea;
        if (lane < 16) {
            ea.x = coss(fmaf(rel, w4.x, b4.x));
            ea.y = coss(fmaf(rel, w4.y, b4.y));
            ea.z = coss(fmaf(rel, w4.z, b4.z));
            ea.w = coss(fmaf(rel, w4.w, b4.w));
        } else {
            ea = sMG[slot][lane - 16];
        }
        __syncthreads();                   // slot free -> safe to refill
        issue(i + DSTG);                   // overlaps with compute below

        float pqk = dot4(q4, kk);
        float s0 = dot4(ea, u0) + (lane < 16 ? pqk : 0.f);
        float s1 = dot4(ea, u1) + (lane < 16 ? 0.f : pqk);
#pragma unroll
        for (int o = 16; o; o >>= 1) {
            s0 += __shfl_xor_sync(0xffffffffu, s0, o);
            s1 += __shfl_xor_sync(0xffffffffu, s1, o);
        }

        float ex0 = __expf(s0 * 0.125f);
        float ex1 = __expf(s1 * 0.125f);
        den0 += ex0;
        den1 += ex1;

        float evv = (lane < 16) ? ex0 : ex1;
        av = fma4(evv, vv, av);
        A0 = fma4(ex0, ea, A0);
        A1 = fma4(ex1, ea, A1);
    }

    float inv0 = 1.f / (den0 + 1e-16f);
    float inv1 = 1.f / (den1 + 1e-16f);
    float invv = (lane < 16) ? inv0 : inv1;

    float4* op = ((float4*)out) + (size_t)n * 32 + lane;
    float4 o = *op;
    o.x += av.x * invv; o.y += av.y * invv;
    o.z += av.z * invv; o.w += av.w * invv;
    *op = o;

    __half2* acc2 = (__half2*)(g_acch + (size_t)n * 256);
    acc2[2 * lane + 0]  = __float22half2_rn(make_float2(A0.x * inv0, A0.y * inv0));
    acc2[2 * lane + 1]  = __float22half2_rn(make_float2(A0.z * inv0, A0.w * inv0));
    acc2[64 + 2 * lane] = __float22half2_rn(make_float2(A1.x * inv1, A1.y * inv1));
    acc2[65 + 2 * lane] = __float22half2_rn(make_float2(A1.z * inv1, A1.w * inv1));
}

// ---------------------------------------------------------------------------
extern "C" void kernel_launch(void* const* d_in, const int* in_sizes, int n_in,
                              void* d_out, int out_size)
{
    const float* x    = (const float*)d_in[0];
    const float* lu   = (const float*)d_in[1];
    const int*   ei   = (const int*)  d_in[2];
    const float* tt   = (const float*)d_in[3];
    const float* msg  = (const float*)d_in[4];
    const float* wt   = (const float*)d_in[5];
    const float* bt   = (const float*)d_in[6];
    const float* Wq   = (const float*)d_in[7];
    const float* bq   = (const float*)d_in[8];
    const float* Wk   = (const float*)d_in[9];
    const float* bk   = (const float*)d_in[10];
    const float* Wv   = (const float*)d_in[11];
    const float* bv   = (const float*)d_in[12];
    const float* We   = (const float*)d_in[13];
    const float* Ws   = (const float*)d_in[14];
    const float* bs   = (const float*)d_in[15];
    float* out = (float*)d_out;

    int N = in_sizes[1];
    int E = in_sizes[3];

    float* pbcat;
    __half *pxh, *pBcatTh, *pBblkTh, *pacch;
    cudaGetSymbolAddress((void**)&pbcat,   g_bcat);
    cudaGetSymbolAddress((void**)&pxh,     g_xh);
    cudaGetSymbolAddress((void**)&pBcatTh, g_BcatTh);
    cudaGetSymbolAddress((void**)&pBblkTh, g_BblkTh);
    cudaGetSymbolAddress((void**)&pacch,   g_acch);

    int gm = (N + 127) / 128;
    int nb = (N + 511) / 512;

    prep_k<<<896, 128>>>(Wq, bq, Wk, bk, Wv, bv, Ws, bs, We, N);      // 0
    convx_k<<<(N * 32 + 255) / 256, 256>>>(x, N * 32);                // 1
    hist_k<<<(E + 255) / 256, 256>>>(ei, E);                          // 2
    // Projection (fp16 mma + ldmatrix): index 3 = profiled slot
    mma_gemm_h<<<dim3(gm, 6), 256>>>(pxh, 128, pBcatTh, 128, out,     // 3
                                     N, 128, pbcat, 0, 1);
    scan1_k<<<nb, 512>>>(N);                                          // 4
    scan2_k<<<1, 256>>>(nb);                                          // 5
    scatter_k<<<(E + 255) / 256, 256>>>(ei, lu, tt, E);               // 6
    // Aggregation (warp per dst node, cp.async pipeline)
    agg_k<<<N, 32>>>(msg, wt, bt, out, N);                            // 7
    // Epilogue (fp16 mma): out += accE[N x 256] @ Bblk[256 x 128]
    mma_gemm_h<<<dim3(gm, 1), 256>>>(pacch, 256, pBblkTh, 256, out,   // 8
                                     N, 256, nullptr, 1, 0);
}